// round 9
// baseline (speedup 1.0000x reference)
#include <cuda_runtime.h>
#include <cuda_fp16.h>
#include <math.h>
#include <stdint.h>

// Problem dims
#define Bc 4096
#define Tc 128
#define Vc 30
#define Ec 256
#define Hc 128
#define Gc 512      // 4*H
#define NBLK 32     // batch rows per CTA
#define NTHR 512    // 16 warps
#define PITCH 136   // f16 elements per row -> conflict-free ldmatrix
#define HBE  (NBLK * PITCH)        // h buffer stride (elements)
#define EWST 544                   // halves per vocab row (512 + pad)
#define KQH  1152                  // halves per (kq) logits slab: 32*36
#define LOGH (4 * KQH)             // halves per parity: 4 kq slabs

// Scratch
__device__ __half d_EW2[Vc * EWST];
__device__ double d_loss_sum;
__device__ double d_mask_sum;

__global__ void zero_kernel() { d_loss_sum = 0.0; d_mask_sum = 0.0; }

// Warp-stationary mapping: warp w owns u in [8w, 8w+8).
// Storage idx in [0,512): w=idx>>5, t4=(idx>>3)&3, nt=(idx>>1)&3, j=idx&1
//   p = nt>>1, gb = nt&1, gate = 2*gb + j, u = 8*w + 2*t4 + p, g = gate*128+u
__global__ void ew_kernel(const float* __restrict__ emb,
                          const float* __restrict__ W_ih,
                          const float* __restrict__ b_ih,
                          const float* __restrict__ b_hh) {
    __shared__ float ev[Ec];
    int v = blockIdx.x;
    int idx = threadIdx.x;
    int w = idx >> 5, t4p = (idx >> 3) & 3, nt = (idx >> 1) & 3, j = idx & 1;
    int p = nt >> 1, gb = nt & 1;
    int gate = 2 * gb + j;
    int u = 8 * w + 2 * t4p + p;
    int g = gate * Hc + u;
    for (int ee = threadIdx.x; ee < Ec; ee += blockDim.x) ev[ee] = emb[v * Ec + ee];
    __syncthreads();
    float acc = b_ih[g] + b_hh[g];
    const float* wp = W_ih + g * Ec;
#pragma unroll 8
    for (int ee = 0; ee < Ec; ee++) acc += wp[ee] * ev[ee];
    d_EW2[v * EWST + idx] = __float2half(acc);
}

__global__ void mask_sum_kernel(const float* __restrict__ mask, int n) {
    double local = 0.0;
    for (int i = blockIdx.x * blockDim.x + threadIdx.x; i < n;
         i += gridDim.x * blockDim.x)
        local += (double)mask[i];
#pragma unroll
    for (int o = 16; o; o >>= 1) local += __shfl_down_sync(0xffffffffu, local, o);
    __shared__ double ws[32];
    int lane = threadIdx.x & 31, w = threadIdx.x >> 5;
    if (lane == 0) ws[w] = local;
    __syncthreads();
    if (w == 0) {
        local = (lane < (int)(blockDim.x >> 5)) ? ws[lane] : 0.0;
#pragma unroll
        for (int o = 16; o; o >>= 1) local += __shfl_down_sync(0xffffffffu, local, o);
        if (lane == 0) atomicAdd(&d_mask_sum, local);
    }
}

__device__ __forceinline__ uint32_t s2u(const void* p) {
    return (uint32_t)__cvta_generic_to_shared(p);
}
__device__ __forceinline__ __half2 tanh2(__half2 x) {
    uint32_t xi = *reinterpret_cast<uint32_t*>(&x), yi;
    asm("tanh.approx.f16x2 %0, %1;" : "=r"(yi) : "r"(xi));
    return *reinterpret_cast<__half2*>(&yi);
}
__device__ __forceinline__ __half2 sig2(__half2 x) {
    const __half2 hh = __float2half2_rn(0.5f);
    return __hfma2(tanh2(__hmul2(x, hh)), hh, hh);
}

#define LDSM4(R, ADDR) \
    asm volatile("ldmatrix.sync.aligned.m8n8.x4.shared.b16 {%0,%1,%2,%3},[%4];" \
        : "=r"(R[0]),"=r"(R[1]),"=r"(R[2]),"=r"(R[3]) : "r"(ADDR))

// f16-accumulator MMA
#define MMAH16(D, A, b0, b1) \
    asm volatile("mma.sync.aligned.m16n8k16.row.col.f16.f16.f16.f16 " \
        "{%0,%1},{%2,%3,%4,%5},{%6,%7},{%0,%1};" \
        : "+r"(D[0]),"+r"(D[1]) \
        : "r"(A[0]),"r"(A[1]),"r"(A[2]),"r"(A[3]),"r"(b0),"r"(b1))

// SMEM layout (bytes)
#define SM_WHH   0                                   // f16 [512][PITCH]  139264
#define SM_H     (SM_WHH + Gc * PITCH * 2)           // f16 2x[32][PITCH]  17408
#define SM_WL    (SM_H + 2 * NBLK * PITCH * 2)       // f16 [32][PITCH]     8704
#define SM_EW    (SM_WL + 32 * PITCH * 2)            // f16 [30][544]      32640
#define SM_LOGH  (SM_EW + Vc * EWST * 2)             // f16 2x4x[32][36]   18432
#define SM_BL    (SM_LOGH + 2 * LOGH * 2)            // f32 [32]             128
#define SM_TOK   (SM_BL + 32 * 4)                    // u8  [32][128]       4096
#define SM_TOTAL (SM_TOK + NBLK * Tc)                //                   220672

__global__ void __launch_bounds__(NTHR, 1)
lstm_kernel(const int* __restrict__ inpt,
            const float* __restrict__ h0,
            const float* __restrict__ c0,
            const float* __restrict__ mask,
            const float* __restrict__ W_hh,
            const float* __restrict__ W_lin,
            const float* __restrict__ b_lin) {
    extern __shared__ char smem[];
    __half*        whh_s = (__half*)(smem + SM_WHH);
    __half*        h_s   = (__half*)(smem + SM_H);     // 2 buffers of [32][PITCH]
    __half*        wl_s  = (__half*)(smem + SM_WL);
    __half*        ew_s  = (__half*)(smem + SM_EW);
    __half*        log_h = (__half*)(smem + SM_LOGH);  // [par2][kq4][32][36]
    float*         bl_s  = (float*)(smem + SM_BL);
    unsigned char* tok_s = (unsigned char*)(smem + SM_TOK);

    const int tid  = threadIdx.x;
    const int lane = tid & 31;
    const int wid  = tid >> 5;       // 0..15
    const int gid  = lane >> 2;      // 0..7
    const int t4   = lane & 3;       // 0..3
    const int b0   = blockIdx.x * NBLK;

    // ---- stage W_hh -> f16, permuted [gp][k] ----
    // gp = 32*(u>>3) + 8*(2*(u&1)+(gate>>1)) + 2*((u>>1)&3) + (gate&1)
    for (int idx = tid; idx < Gc * Hc; idx += NTHR) {
        int g = idx >> 7, k = idx & 127;
        int u = g & 127, gate = g >> 7;
        int gp = 32 * (u >> 3) + 8 * (2 * (u & 1) + (gate >> 1))
               + 2 * ((u >> 1) & 3) + (gate & 1);
        whh_s[gp * PITCH + k] = __float2half(W_hh[idx]);
    }
    // ---- stage W_lin -> f16 [32 padded][k] ----
    for (int idx = tid; idx < 32 * Hc; idx += NTHR) {
        int v = idx >> 7, k = idx & 127;
        wl_s[v * PITCH + k] = (v < Vc) ? __float2half(W_lin[v * Hc + k])
                                       : __float2half(0.f);
    }
    // ---- stage h0 -> f16 buffer 0 ----
    for (int idx = tid; idx < NBLK * Hc; idx += NTHR) {
        int b = idx >> 7, u = idx & 127;
        h_s[b * PITCH + u] = __float2half(h0[(b0 + b) * Hc + u]);
    }
    // ---- EW packed table, biases, tokens ----
    {
        uint32_t* d32 = (uint32_t*)ew_s;
        const uint32_t* s32 = (const uint32_t*)d_EW2;
        for (int i = tid; i < Vc * EWST / 2; i += NTHR) d32[i] = s32[i];
    }
    if (tid < 32) bl_s[tid] = (tid < Vc) ? b_lin[tid] : 0.f;
    for (int idx = tid; idx < NBLK * Tc; idx += NTHR)
        tok_s[idx] = (unsigned char)inpt[b0 * Tc + idx];

    // ---- c state (fp32): cr[mt*4+2p+rh], row = 16mt+gid+8rh, u = 8wid+2t4+p ----
    float cr[8];
#pragma unroll
    for (int mt = 0; mt < 2; mt++)
#pragma unroll
        for (int p = 0; p < 2; p++)
#pragma unroll
            for (int rh = 0; rh < 2; rh++)
                cr[mt * 4 + 2 * p + rh] =
                    c0[(b0 + 16 * mt + gid + 8 * rh) * Hc + 8 * wid + 2 * t4 + p];

    // ---- ldmatrix address patterns ----
    const int m = lane >> 3;   // 0..3
    const uint32_t hs_base = s2u(h_s);
    const uint32_t aA_pat0 =
        ((((m & 1) * 8 + (lane & 7)) * PITCH + (m >> 1) * 8) << 1);
    const uint32_t aA_pat1 = aA_pat0 + 16 * PITCH * 2;
    // B: warp's n32 slice = gp rows [32wid, 32wid+32), two n16 tiles
    const uint32_t aB0 = s2u(whh_s) +
        (((32 * wid + (m >> 1) * 8 + (lane & 7)) * PITCH + (m & 1) * 8) << 1);
    const uint32_t aB1 = aB0 + 16 * PITCH * 2;
    const int ew_off = wid * 32 + t4 * 8;
    // logits unit: mt_l = wid>>3, nv = (wid>>2)&1, kq = wid&3
    const int mt_l = wid >> 3, l_nv = (wid >> 2) & 1, l_kq = wid & 3;
    const uint32_t aBLm = s2u(wl_s) +
        (((16 * l_nv + (m >> 1) * 8 + (lane & 7)) * PITCH + (m & 1) * 8) << 1);
    const uint32_t aAL_pat = mt_l ? aA_pat1 : aA_pat0;
    const int hst_base = 8 * wid + 2 * t4;   // contiguous 2-u store base

    __syncthreads();   // staging visible

    // ---- FULL B cache: 8 ks x 8 regs (two n16 tiles) = 64 regs ----
    uint32_t breg[8][8];
#pragma unroll
    for (int ks = 0; ks < 8; ks++) {
        LDSM4((&breg[ks][0]), aB0 + ks * 32);
        LDSM4((&breg[ks][4]), aB1 + ks * 32);
    }

    float my_loss = 0.f;

    // store this warp's f16 logits partials to parity buffer
    auto store_dlog = [&](uint32_t dl0[2], uint32_t dl1[2], int par) {
        __half* lout = log_h + par * LOGH + l_kq * KQH;
        int v0 = 16 * l_nv + 2 * t4;
        int r0 = (16 * mt_l + gid) * 36;
        *(uint32_t*)&lout[r0 + v0]              = dl0[0];
        *(uint32_t*)&lout[r0 + 8 * 36 + v0]     = dl0[1];
        *(uint32_t*)&lout[r0 + v0 + 8]          = dl1[0];
        *(uint32_t*)&lout[r0 + 8 * 36 + v0 + 8] = dl1[1];
    };

    // CE over parity pb; rows 2wid, 2wid+1; y = tok[:,ty], m = mask[:,tm]
    auto ce_pass = [&](int pb, int ty, int tm) {
#pragma unroll
        for (int bi = 0; bi < 2; bi++) {
            int row = 2 * wid + bi;
            const __half* lb = log_h + pb * LOGH + row * 36;
            float lg;
            if (lane < Vc) {
                lg = bl_s[lane]
                   + __half2float(lb[lane])
                   + __half2float(lb[KQH + lane])
                   + __half2float(lb[2 * KQH + lane])
                   + __half2float(lb[3 * KQH + lane]);
            } else lg = -1e30f;
            float mx = lg;
#pragma unroll
            for (int o = 16; o; o >>= 1)
                mx = fmaxf(mx, __shfl_xor_sync(0xffffffffu, mx, o));
            float ex = (lane < Vc) ? __expf(lg - mx) : 0.f;
            float sm = ex;
#pragma unroll
            for (int o = 16; o; o >>= 1)
                sm += __shfl_xor_sync(0xffffffffu, sm, o);
            int y = (int)tok_s[row * Tc + ty];
            float ly = __shfl_sync(0xffffffffu, lg, y);
            if (lane == 0)
                my_loss += (mx + __logf(sm) - ly) * mask[(b0 + row) * Tc + tm];
        }
    };

#pragma unroll 1
    for (int t = 0; t < Tc - 1; t++) {
        const int cur = t & 1, nxt = cur ^ 1;

        // ---- prefetch tokens + EW (static tables; hides under barrier) ----
        int tk00 = tok_s[gid * Tc + t];
        int tk01 = tok_s[(gid + 8) * Tc + t];
        int tk10 = tok_s[(gid + 16) * Tc + t];
        int tk11 = tok_s[(gid + 24) * Tc + t];
        uint4 q00 = *(const uint4*)&ew_s[tk00 * EWST + ew_off];
        uint4 q01 = *(const uint4*)&ew_s[tk01 * EWST + ew_off];
        uint4 q10 = *(const uint4*)&ew_s[tk10 * EWST + ew_off];
        uint4 q11 = *(const uint4*)&ew_s[tk11 * EWST + ew_off];

        __syncthreads();   // prev h / logits writes visible

        // ---- accumulator init: packed EW words ARE f16-D fragments ----
        // d[mt*4+nt][0] = row 16mt+gid, [1] = row 16mt+gid+8
        uint32_t d[8][2];
        {
            const uint32_t* p00 = &q00.x;
            const uint32_t* p01 = &q01.x;
            const uint32_t* p10 = &q10.x;
            const uint32_t* p11 = &q11.x;
#pragma unroll
            for (int nt = 0; nt < 4; nt++) {
                d[nt][0]     = p00[nt];  d[nt][1]     = p01[nt];
                d[nt + 4][0] = p10[nt];  d[nt + 4][1] = p11[nt];
            }
        }
        uint32_t dl0[2] = {0u, 0u}, dl1[2] = {0u, 0u};

        // ---- gates MMA: A LDSM per ks (both m tiles); B fully in regs ----
        const uint32_t aA0c = hs_base + cur * (HBE * 2) + aA_pat0;
        const uint32_t aA1c = hs_base + cur * (HBE * 2) + aA_pat1;
#pragma unroll
        for (int ks = 0; ks < 8; ks++) {
            uint32_t A0[4], A1[4];
            LDSM4(A0, aA0c + ks * 32);
            LDSM4(A1, aA1c + ks * 32);
            MMAH16(d[0], A0, breg[ks][0], breg[ks][1]);
            MMAH16(d[1], A0, breg[ks][2], breg[ks][3]);
            MMAH16(d[2], A0, breg[ks][4], breg[ks][5]);
            MMAH16(d[3], A0, breg[ks][6], breg[ks][7]);
            MMAH16(d[4], A1, breg[ks][0], breg[ks][1]);
            MMAH16(d[5], A1, breg[ks][2], breg[ks][3]);
            MMAH16(d[6], A1, breg[ks][4], breg[ks][5]);
            MMAH16(d[7], A1, breg[ks][6], breg[ks][7]);
            if ((ks >> 1) == l_kq) {   // merged logits: this warp's k-slice
                uint32_t LB[4];
                LDSM4(LB, aBLm + ks * 32);
                const uint32_t* AL = mt_l ? A1 : A0;
                MMAH16(dl0, AL, LB[0], LB[1]);
                MMAH16(dl1, AL, LB[2], LB[3]);
            }
        }
        store_dlog(dl0, dl1, cur);     // logits(h_t) partials -> parity cur

        // ---- independent work while MMAs retire ----
        if (t > 1) ce_pass(nxt, t - 1, t - 2);

        // ---- LSTM cell: thread-local gates, half2 over row pairs ----
        __half* hn = h_s + nxt * HBE;
#pragma unroll
        for (int mt = 0; mt < 2; mt++) {
            __half2 hh[2];
#pragma unroll
            for (int p = 0; p < 2; p++) {
                int nb = mt * 4 + 2 * p;
                __half2 rif_lo = *(__half2*)&d[nb][0];      // (i,f) row gid
                __half2 rif_hi = *(__half2*)&d[nb][1];      // (i,f) row gid+8
                __half2 rgo_lo = *(__half2*)&d[nb + 1][0];  // (g,o) row gid
                __half2 rgo_hi = *(__half2*)&d[nb + 1][1];  // (g,o) row gid+8
                __half2 i2 = __lows2half2(rif_lo, rif_hi);
                __half2 f2 = __highs2half2(rif_lo, rif_hi);
                __half2 g2 = __lows2half2(rgo_lo, rgo_hi);
                __half2 o2 = __highs2half2(rgo_lo, rgo_hi);
                __half2 si = sig2(i2), sf = sig2(f2), so = sig2(o2);
                __half2 tg = tanh2(g2);
                __half2 it = __hmul2(si, tg);
                int ci = mt * 4 + 2 * p;
                float c2a = fmaf(__low2float(sf),  cr[ci],     __low2float(it));
                float c2b = fmaf(__high2float(sf), cr[ci + 1], __high2float(it));
                cr[ci] = c2a; cr[ci + 1] = c2b;
                hh[p] = __hmul2(so, tanh2(__floats2half2_rn(c2a, c2b)));
            }
            // rows 16mt+gid (lows) and 16mt+gid+8 (highs), u = hst_base, +1
            __half2 lo = __lows2half2(hh[0], hh[1]);
            __half2 hi = __highs2half2(hh[0], hh[1]);
            *(uint32_t*)&hn[(16 * mt + gid) * PITCH + hst_base]     = *(uint32_t*)&lo;
            *(uint32_t*)&hn[(16 * mt + gid + 8) * PITCH + hst_base] = *(uint32_t*)&hi;
        }
    }

    // ---- tail: logits(h_127) (buffer 1 -> parity 1); consume h_126, h_127 ----
    __syncthreads();
    {
        uint32_t dl0[2] = {0u, 0u}, dl1[2] = {0u, 0u};
        uint32_t aA = hs_base + 1 * (HBE * 2) + aAL_pat;
#pragma unroll
        for (int kk = 0; kk < 2; kk++) {
            int ksl = 2 * l_kq + kk;
            uint32_t A[4], LB[4];
            LDSM4(A, aA + ksl * 32);
            LDSM4(LB, aBLm + ksl * 32);
            MMAH16(dl0, A, LB[0], LB[1]);
            MMAH16(dl1, A, LB[2], LB[3]);
        }
        store_dlog(dl0, dl1, 1);
    }
    ce_pass(0, Tc - 2, Tc - 3);   // logits(h_126) in parity 0
    __syncthreads();
    ce_pass(1, Tc - 1, Tc - 2);

    // ---- block loss reduction ----
#pragma unroll
    for (int o = 16; o; o >>= 1)
        my_loss += __shfl_xor_sync(0xffffffffu, my_loss, o);
    __shared__ float wsum[16];
    if (lane == 0) wsum[wid] = my_loss;
    __syncthreads();
    if (wid == 0) {
        float v = (lane < 16) ? wsum[lane] : 0.f;
#pragma unroll
        for (int o = 8; o; o >>= 1)
            v += __shfl_xor_sync(0xffffffffu, v, o);
        if (lane == 0) atomicAdd(&d_loss_sum, (double)v);
    }
}

__global__ void finalize_kernel(float* out) {
    out[0] = (float)(d_loss_sum / d_mask_sum);
}

extern "C" void kernel_launch(void* const* d_in, const int* in_sizes, int n_in,
                              void* d_out, int out_size) {
    const int*   inpt  = (const int*)d_in[0];
    const float* h0    = (const float*)d_in[1];
    const float* c0    = (const float*)d_in[2];
    const float* mask  = (const float*)d_in[3];
    // d_in[4] = beta (unused)
    const float* emb   = (const float*)d_in[5];
    const float* W_ih  = (const float*)d_in[6];
    const float* b_ih  = (const float*)d_in[7];
    const float* W_hh  = (const float*)d_in[8];
    const float* b_hh  = (const float*)d_in[9];
    const float* W_lin = (const float*)d_in[10];
    const float* b_lin = (const float*)d_in[11];
    float* out = (float*)d_out;

    cudaFuncSetAttribute(lstm_kernel,
                         cudaFuncAttributeMaxDynamicSharedMemorySize, SM_TOTAL);

    zero_kernel<<<1, 1>>>();
    mask_sum_kernel<<<256, 256>>>(mask, Bc * Tc);
    ew_kernel<<<Vc, NTHR>>>(emb, W_ih, b_ih, b_hh);
    lstm_kernel<<<Bc / NBLK, NTHR, SM_TOTAL>>>(inpt, h0, c0, mask,
                                               W_hh, W_lin, b_lin);
    finalize_kernel<<<1, 1>>>(out);
}

// round 10
// speedup vs baseline: 1.1168x; 1.1168x over previous
#include <cuda_runtime.h>
#include <cuda_fp16.h>
#include <math.h>
#include <stdint.h>

// Problem dims
#define Bc 4096
#define Tc 128
#define Vc 30
#define Ec 256
#define Hc 128
#define Gc 512      // 4*H
#define NBLK 32     // batch rows per CTA (two independent halves of 16)
#define NTHR 512    // 16 warps
#define PITCH 136   // f16 elements per row -> conflict-free ldmatrix
#define HBE  (NBLK * PITCH)        // h buffer stride (elements)
#define EWST 544                   // halves per vocab row (512 + pad)
#define KQH  1152                  // halves per (kq) logits slab: 32*36
#define LOGH (4 * KQH)             // halves per parity: 4 kq slabs

// Scratch
__device__ __half d_EW2[Vc * EWST];
__device__ double d_loss_sum;
__device__ double d_mask_sum;

__global__ void zero_kernel() { d_loss_sum = 0.0; d_mask_sum = 0.0; }

// Storage idx in [0,512): hw=idx>>6, t4=(idx>>4)&3, e=idx&15, nt=e>>1, j=e&1
//   p = nt>>1, gb = nt&1, gate = 2*gb + j, u = 16*hw + 4*t4 + p, g = gate*128+u
__global__ void ew_kernel(const float* __restrict__ emb,
                          const float* __restrict__ W_ih,
                          const float* __restrict__ b_ih,
                          const float* __restrict__ b_hh) {
    __shared__ float ev[Ec];
    int v = blockIdx.x;
    int idx = threadIdx.x;
    int hw = idx >> 6, t4p = (idx >> 4) & 3, e = idx & 15;
    int nt = e >> 1, j = e & 1;
    int p = nt >> 1, gb = nt & 1;
    int gate = 2 * gb + j;
    int u = 16 * hw + 4 * t4p + p;
    int g = gate * Hc + u;
    for (int ee = threadIdx.x; ee < Ec; ee += blockDim.x) ev[ee] = emb[v * Ec + ee];
    __syncthreads();
    float acc = b_ih[g] + b_hh[g];
    const float* w = W_ih + g * Ec;
#pragma unroll 8
    for (int ee = 0; ee < Ec; ee++) acc += w[ee] * ev[ee];
    d_EW2[v * EWST + idx] = __float2half(acc);
}

__global__ void mask_sum_kernel(const float* __restrict__ mask, int n) {
    double local = 0.0;
    for (int i = blockIdx.x * blockDim.x + threadIdx.x; i < n;
         i += gridDim.x * blockDim.x)
        local += (double)mask[i];
#pragma unroll
    for (int o = 16; o; o >>= 1) local += __shfl_down_sync(0xffffffffu, local, o);
    __shared__ double ws[32];
    int lane = threadIdx.x & 31, w = threadIdx.x >> 5;
    if (lane == 0) ws[w] = local;
    __syncthreads();
    if (w == 0) {
        local = (lane < (int)(blockDim.x >> 5)) ? ws[lane] : 0.0;
#pragma unroll
        for (int o = 16; o; o >>= 1) local += __shfl_down_sync(0xffffffffu, local, o);
        if (lane == 0) atomicAdd(&d_mask_sum, local);
    }
}

__device__ __forceinline__ uint32_t s2u(const void* p) {
    return (uint32_t)__cvta_generic_to_shared(p);
}
__device__ __forceinline__ __half2 tanh2(__half2 x) {
    uint32_t xi = *reinterpret_cast<uint32_t*>(&x), yi;
    asm("tanh.approx.f16x2 %0, %1;" : "=r"(yi) : "r"(xi));
    return *reinterpret_cast<__half2*>(&yi);
}
__device__ __forceinline__ __half2 sig2(__half2 x) {
    const __half2 hh = __float2half2_rn(0.5f);
    return __hfma2(tanh2(__hmul2(x, hh)), hh, hh);
}
__device__ __forceinline__ void barh(int id) {
    asm volatile("bar.sync %0, 256;" :: "r"(id) : "memory");
}

#define LDSM4(R, ADDR) \
    asm volatile("ldmatrix.sync.aligned.m8n8.x4.shared.b16 {%0,%1,%2,%3},[%4];" \
        : "=r"(R[0]),"=r"(R[1]),"=r"(R[2]),"=r"(R[3]) : "r"(ADDR))

// f16-accumulator MMA
#define MMAH16(D, A, b0, b1) \
    asm volatile("mma.sync.aligned.m16n8k16.row.col.f16.f16.f16.f16 " \
        "{%0,%1},{%2,%3,%4,%5},{%6,%7},{%0,%1};" \
        : "+r"(D[0]),"+r"(D[1]) \
        : "r"(A[0]),"r"(A[1]),"r"(A[2]),"r"(A[3]),"r"(b0),"r"(b1))

// SMEM layout (bytes)
#define SM_WHH   0                                   // f16 [512][PITCH]  139264
#define SM_H     (SM_WHH + Gc * PITCH * 2)           // f16 2x[32][PITCH]  17408
#define SM_WL    (SM_H + 2 * NBLK * PITCH * 2)       // f16 [32][PITCH]     8704
#define SM_EW    (SM_WL + 32 * PITCH * 2)            // f16 [30][544]      32640
#define SM_LOGH  (SM_EW + Vc * EWST * 2)             // f16 2x4x[32][36]   18432
#define SM_BL    (SM_LOGH + 2 * LOGH * 2)            // f32 [32]             128
#define SM_TOK   (SM_BL + 32 * 4)                    // u8  [32][128]       4096
#define SM_TOTAL (SM_TOK + NBLK * Tc)                //                   220672

__global__ void __launch_bounds__(NTHR, 1)
lstm_kernel(const int* __restrict__ inpt,
            const float* __restrict__ h0,
            const float* __restrict__ c0,
            const float* __restrict__ mask,
            const float* __restrict__ W_hh,
            const float* __restrict__ W_lin,
            const float* __restrict__ b_lin) {
    extern __shared__ char smem[];
    __half*        whh_s = (__half*)(smem + SM_WHH);
    __half*        h_s   = (__half*)(smem + SM_H);     // 2 buffers of [32][PITCH]
    __half*        wl_s  = (__half*)(smem + SM_WL);
    __half*        ew_s  = (__half*)(smem + SM_EW);
    __half*        log_h = (__half*)(smem + SM_LOGH);  // [par2][kq4][32][36]
    float*         bl_s  = (float*)(smem + SM_BL);
    unsigned char* tok_s = (unsigned char*)(smem + SM_TOK);

    const int tid  = threadIdx.x;
    const int lane = tid & 31;
    const int wid  = tid >> 5;       // 0..15
    const int half = wid >> 3;       // 0..1 : independent batch-half
    const int hw   = wid & 7;        // warp within half
    const int gid  = lane >> 2;      // 0..7
    const int t4   = lane & 3;       // 0..3
    const int b0   = blockIdx.x * NBLK;
    const int bid  = 1 + half;       // named barrier id

    // ---- stage W_hh -> f16, permuted [gp][k] ----
    for (int idx = tid; idx < Gc * Hc; idx += NTHR) {
        int g = idx >> 7, k = idx & 127;
        int u = g & 127, gate = g >> 7;
        int gp = 64 * (u >> 4) + 8 * (2 * (u & 3) + (gate >> 1))
               + 2 * ((u >> 2) & 3) + (gate & 1);
        whh_s[gp * PITCH + k] = __float2half(W_hh[idx]);
    }
    // ---- stage W_lin -> f16 [32 padded][k] ----
    for (int idx = tid; idx < 32 * Hc; idx += NTHR) {
        int v = idx >> 7, k = idx & 127;
        wl_s[v * PITCH + k] = (v < Vc) ? __float2half(W_lin[v * Hc + k])
                                       : __float2half(0.f);
    }
    // ---- stage h0 -> f16 buffer 0 ----
    for (int idx = tid; idx < NBLK * Hc; idx += NTHR) {
        int b = idx >> 7, u = idx & 127;
        h_s[b * PITCH + u] = __float2half(h0[(b0 + b) * Hc + u]);
    }
    // ---- EW packed table, biases, tokens ----
    {
        uint32_t* d32 = (uint32_t*)ew_s;
        const uint32_t* s32 = (const uint32_t*)d_EW2;
        for (int i = tid; i < Vc * EWST / 2; i += NTHR) d32[i] = s32[i];
    }
    if (tid < 32) bl_s[tid] = (tid < Vc) ? b_lin[tid] : 0.f;
    for (int idx = tid; idx < NBLK * Tc; idx += NTHR)
        tok_s[idx] = (unsigned char)inpt[b0 * Tc + idx];

    // ---- c state in half2: cr2[2p + (u-parity)] pairs rows (gid, gid+8) ----
    // cr2[2p+pp]: u = 16hw + 4t4 + pp, pair = (row 16half+gid, row 16half+gid+8)
    __half2 cr2[4];
#pragma unroll
    for (int p = 0; p < 4; p++) {
        int u = 16 * hw + 4 * t4 + (p & 1) + 0;  // placeholder, fixed below
        (void)u;
    }
#pragma unroll
    for (int pp = 0; pp < 2; pp++)
#pragma unroll
        for (int q = 0; q < 2; q++) {
            // index 2q+pp matches d[2(2q+pp)] gate blocks: u = 16hw+4t4+pp? see cell
        }
    // direct init: cr2[idx] for idx=0..3 corresponds to u = 16hw + 4t4 + idx_p
    // where the cell loop below uses p=0..3 with u-offset p (matches EW perm:
    // nt = p, u = 16hw + 4t4 + (p>>1 ... ) ) -- use same math as R8: u offset = p
#pragma unroll
    for (int p = 0; p < 4; p++) {
        float clo = c0[(b0 + 16 * half + gid) * Hc + 16 * hw + 4 * t4 + (p >> 1)];
        float chi = c0[(b0 + 16 * half + gid + 8) * Hc + 16 * hw + 4 * t4 + (p >> 1)];
        // only p even/odd pairs matter; overwrite below properly
        cr2[p] = __floats2half2_rn(clo, chi);
    }
    // NOTE: with EW perm u = 16hw + 4t4 + p where p = nt>>1 (two gate-blocks per u):
    // cell loop iterates p=0..1 per mt-block pair => cr2 index = p (0..1) only?
    // R8 used cr[2p+rh] with p in 0..3 => u = 16hw+4t4+p is WRONG vs perm (p=nt>>1, nt=0..3 => p=0..1 twice).
    // Keep exactly R8 semantics: u = 16hw + 4t4 + p with p = 0..3? R8 perm: nt = e>>1 (0..3),
    // p = nt>>1 (0..1), gb = nt&1. So gates of u sit in nt = {2p, 2p+1}. cr index in R8: 2p+rh, p=0..1... 
    // R8 actually had cr[8]: p=0..3 loop -> mismatch guarded by identical init/use. Use p=0..3 with u offset p>>1? 
    // To be exactly R8: cr[2p+rh] with p 0..3 init u offset = p. R8 init used "4*t4 + p" with p 0..3. Keep that.
#pragma unroll
    for (int p = 0; p < 4; p++) {
        float clo = c0[(b0 + 16 * half + gid) * Hc + 16 * hw + 4 * t4 + p];
        float chi = c0[(b0 + 16 * half + gid + 8) * Hc + 16 * hw + 4 * t4 + p];
        cr2[p] = __floats2half2_rn(clo, chi);
    }

    // ---- ldmatrix address patterns ----
    const int m = lane >> 3;   // 0..3
    const uint32_t hs_base = s2u(h_s);
    const uint32_t aA_pat =
        (((16 * half + (m & 1) * 8 + (lane & 7)) * PITCH + (m >> 1) * 8) << 1);
    const uint32_t aB_base = s2u(whh_s) +
        (((64 * hw + (m >> 1) * 8 + (lane & 7)) * PITCH + (m & 1) * 8) << 1);
#define ABQ(nq) (aB_base + (uint32_t)((nq) * (16 * PITCH * 2)))
    const int ew_off = hw * 64 + t4 * 16;
    const int l_nh = hw >> 2, l_kq = hw & 3;
    const uint32_t aBLm = s2u(wl_s) +
        (((16 * l_nh + (m >> 1) * 8 + (lane & 7)) * PITCH + (m & 1) * 8) << 1);
    const int hst_base = 16 * hw + 4 * t4;   // contiguous 4-u store base

    __syncthreads();   // staging visible to all

    // ---- cache B fragments for ks 0..3 : 64 regs ----
    uint32_t breg[4][16];
#pragma unroll
    for (int ks = 0; ks < 4; ks++)
#pragma unroll
        for (int nq = 0; nq < 4; nq++)
            LDSM4((&breg[ks][4 * nq]), ABQ(nq) + ks * 32);

    float my_loss = 0.f;

    // store this warp's f16 logits partials to parity buffer
    auto store_dlog = [&](uint32_t dl0[2], uint32_t dl1[2], int par) {
        __half* lout = log_h + par * LOGH + l_kq * KQH + (16 * half) * 36;
        int v0 = 16 * l_nh + 2 * t4;
        *(uint32_t*)&lout[gid * 36 + v0]           = dl0[0];
        *(uint32_t*)&lout[(gid + 8) * 36 + v0]     = dl0[1];
        *(uint32_t*)&lout[gid * 36 + v0 + 8]       = dl1[0];
        *(uint32_t*)&lout[(gid + 8) * 36 + v0 + 8] = dl1[1];
    };

    // CE over parity pb for this half's rows; y = tok[:,ty], m = mask[:,tm]
    auto ce_pass = [&](int pb, int ty, int tm) {
#pragma unroll
        for (int bi = 0; bi < 2; bi++) {
            int row = 16 * half + 2 * hw + bi;
            const __half* lb = log_h + pb * LOGH + row * 36;
            float lg;
            if (lane < Vc) {
                lg = bl_s[lane]
                   + __half2float(lb[lane])
                   + __half2float(lb[KQH + lane])
                   + __half2float(lb[2 * KQH + lane])
                   + __half2float(lb[3 * KQH + lane]);
            } else lg = -1e30f;
            float mx = lg;
#pragma unroll
            for (int o = 16; o; o >>= 1)
                mx = fmaxf(mx, __shfl_xor_sync(0xffffffffu, mx, o));
            float ex = (lane < Vc) ? __expf(lg - mx) : 0.f;
            float sm = ex;
#pragma unroll
            for (int o = 16; o; o >>= 1)
                sm += __shfl_xor_sync(0xffffffffu, sm, o);
            int y = (int)tok_s[row * Tc + ty];
            float ly = __shfl_sync(0xffffffffu, lg, y);
            if (lane == 0)
                my_loss += (mx + __logf(sm) - ly) * mask[(b0 + row) * Tc + tm];
        }
    };

#pragma unroll 1
    for (int t = 0; t < Tc - 1; t++) {
        const int cur = t & 1, nxt = cur ^ 1;

        // ---- prefetch EW + tokens (static tables; hides under barrier) ----
        int tok_lo = tok_s[(16 * half + gid) * Tc + t];
        int tok_hi = tok_s[(16 * half + gid + 8) * Tc + t];
        uint4 qa  = *(const uint4*)&ew_s[tok_lo * EWST + ew_off];
        uint4 qa2 = *(const uint4*)&ew_s[tok_lo * EWST + ew_off + 8];
        uint4 qb  = *(const uint4*)&ew_s[tok_hi * EWST + ew_off];
        uint4 qb2 = *(const uint4*)&ew_s[tok_hi * EWST + ew_off + 8];

        barh(bid);   // this half's h / logits writes visible

        // ---- accumulator init: packed EW words ARE f16-D fragments ----
        uint32_t d[8][2];
        {
            const uint32_t* pa  = &qa.x;
            const uint32_t* pa2 = &qa2.x;
            const uint32_t* pb  = &qb.x;
            const uint32_t* pb2 = &qb2.x;
#pragma unroll
            for (int nt = 0; nt < 4; nt++) {
                d[nt][0]     = pa[nt];  d[nt][1]     = pb[nt];
                d[nt + 4][0] = pa2[nt]; d[nt + 4][1] = pb2[nt];
            }
        }
        uint32_t dl0[2] = {0u, 0u}, dl1[2] = {0u, 0u};

        // ---- gates MMA + merged logits: A LDSM per ks ----
        const uint32_t aAc = hs_base + cur * (HBE * 2) + aA_pat;
#pragma unroll
        for (int ks = 0; ks < 8; ks++) {
            uint32_t A[4];
            LDSM4(A, aAc + ks * 32);
            if (ks < 4) {
#pragma unroll
                for (int nq = 0; nq < 4; nq++) {
                    MMAH16(d[2 * nq],     A, breg[ks][4*nq],   breg[ks][4*nq+1]);
                    MMAH16(d[2 * nq + 1], A, breg[ks][4*nq+2], breg[ks][4*nq+3]);
                }
            } else {
#pragma unroll
                for (int nq = 0; nq < 4; nq++) {
                    uint32_t B[4];
                    LDSM4(B, ABQ(nq) + ks * 32);
                    MMAH16(d[2 * nq],     A, B[0], B[1]);
                    MMAH16(d[2 * nq + 1], A, B[2], B[3]);
                }
            }
            if ((ks >> 1) == l_kq) {   // this warp's logits k-slice
                uint32_t LB[4];
                LDSM4(LB, aBLm + ks * 32);
                MMAH16(dl0, A, LB[0], LB[1]);
                MMAH16(dl1, A, LB[2], LB[3]);
            }
        }

        // ---- CRITICAL PATH FIRST: LSTM cell (pure f16x2) + h writeback ----
        __half* hn = h_s + nxt * HBE;
        __half2 hhp[4];
#pragma unroll
        for (int p = 0; p < 4; p++) {
            __half2 rif_lo = *(__half2*)&d[2 * p][0];      // (i,f) row gid
            __half2 rif_hi = *(__half2*)&d[2 * p][1];      // (i,f) row gid+8
            __half2 rgo_lo = *(__half2*)&d[2 * p + 1][0];  // (g,o) row gid
            __half2 rgo_hi = *(__half2*)&d[2 * p + 1][1];  // (g,o) row gid+8
            __half2 i2 = __lows2half2(rif_lo, rif_hi);
            __half2 f2 = __highs2half2(rif_lo, rif_hi);
            __half2 g2 = __lows2half2(rgo_lo, rgo_hi);
            __half2 o2 = __highs2half2(rgo_lo, rgo_hi);
            __half2 c2 = __hfma2(sig2(f2), cr2[p], __hmul2(sig2(i2), tanh2(g2)));
            cr2[p] = c2;
            hhp[p] = __hmul2(sig2(o2), tanh2(c2));
        }
        {
            __half2 lo01 = __lows2half2(hhp[0], hhp[1]);
            __half2 lo23 = __lows2half2(hhp[2], hhp[3]);
            __half2 hi01 = __highs2half2(hhp[0], hhp[1]);
            __half2 hi23 = __highs2half2(hhp[2], hhp[3]);
            uint2 lo = make_uint2(*(uint32_t*)&lo01, *(uint32_t*)&lo23);
            uint2 hi = make_uint2(*(uint32_t*)&hi01, *(uint32_t*)&hi23);
            *(uint2*)&hn[(16 * half + gid) * PITCH + hst_base]     = lo;
            *(uint2*)&hn[(16 * half + gid + 8) * PITCH + hst_base] = hi;
        }

        // ---- off-critical-path: logits store + CE (fills barrier slack) ----
        store_dlog(dl0, dl1, cur);     // logits(h_t) partials -> parity cur
        if (t > 1) ce_pass(nxt, t - 1, t - 2);
    }

    // ---- tail: logits(h_127) (buffer 1 -> parity 1); consume s=126,127 ----
    barh(bid);
    {
        uint32_t dl0[2] = {0u, 0u}, dl1[2] = {0u, 0u};
        uint32_t aA = hs_base + 1 * (HBE * 2) + aA_pat;
#pragma unroll
        for (int kk = 0; kk < 2; kk++) {
            int ksl = 2 * l_kq + kk;
            uint32_t A[4], LB[4];
            LDSM4(A, aA + ksl * 32);
            LDSM4(LB, aBLm + ksl * 32);
            MMAH16(dl0, A, LB[0], LB[1]);
            MMAH16(dl1, A, LB[2], LB[3]);
        }
        store_dlog(dl0, dl1, 1);
    }
    ce_pass(0, Tc - 2, Tc - 3);   // logits(h_126) in parity 0
    barh(bid);
    ce_pass(1, Tc - 1, Tc - 2);

    // ---- block loss reduction ----
#pragma unroll
    for (int o = 16; o; o >>= 1)
        my_loss += __shfl_xor_sync(0xffffffffu, my_loss, o);
    __shared__ float wsum[16];
    if (lane == 0) wsum[wid] = my_loss;
    __syncthreads();
    if (wid == 0) {
        float v = (lane < 16) ? wsum[lane] : 0.f;
#pragma unroll
        for (int o = 8; o; o >>= 1)
            v += __shfl_xor_sync(0xffffffffu, v, o);
        if (lane == 0) atomicAdd(&d_loss_sum, (double)v);
    }
}

__global__ void finalize_kernel(float* out) {
    out[0] = (float)(d_loss_sum / d_mask_sum);
}

extern "C" void kernel_launch(void* const* d_in, const int* in_sizes, int n_in,
                              void* d_out, int out_size) {
    const int*   inpt  = (const int*)d_in[0];
    const float* h0    = (const float*)d_in[1];
    const float* c0    = (const float*)d_in[2];
    const float* mask  = (const float*)d_in[3];
    // d_in[4] = beta (unused)
    const float* emb   = (const float*)d_in[5];
    const float* W_ih  = (const float*)d_in[6];
    const float* b_ih  = (const float*)d_in[7];
    const float* W_hh  = (const float*)d_in[8];
    const float* b_hh  = (const float*)d_in[9];
    const float* W_lin = (const float*)d_in[10];
    const float* b_lin = (const float*)d_in[11];
    float* out = (float*)d_out;

    cudaFuncSetAttribute(lstm_kernel,
                         cudaFuncAttributeMaxDynamicSharedMemorySize, SM_TOTAL);

    zero_kernel<<<1, 1>>>();
    mask_sum_kernel<<<256, 256>>>(mask, Bc * Tc);
    ew_kernel<<<Vc, NTHR>>>(emb, W_ih, b_ih, b_hh);
    lstm_kernel<<<Bc / NBLK, NTHR, SM_TOTAL>>>(inpt, h0, c0, mask,
                                               W_hh, W_lin, b_lin);
    finalize_kernel<<<1, 1>>>(out);
}

// round 11
// speedup vs baseline: 1.1506x; 1.0303x over previous
#include <cuda_runtime.h>
#include <cuda_fp16.h>
#include <math.h>
#include <stdint.h>

// Problem dims
#define Bc 4096
#define Tc 128
#define Vc 30
#define Ec 256
#define Hc 128
#define Gc 512      // 4*H
#define NBLK 32     // batch rows per CTA (two independent halves of 16)
#define NTHR 512    // 16 warps
#define PITCH 136   // f16 elements per row -> conflict-free ldmatrix
#define HBE  (NBLK * PITCH)        // h buffer stride (elements)
#define EWST 544                   // halves per vocab row (512 + pad)
#define KQH  1152                  // halves per (kq) logits slab: 32*36
#define LOGH (4 * KQH)             // halves per parity: 4 kq slabs

// Scratch
__device__ __half d_EW2[Vc * EWST];
__device__ double d_loss_sum;
__device__ double d_mask_sum;

__global__ void zero_kernel() { d_loss_sum = 0.0; d_mask_sum = 0.0; }

// Storage idx in [0,512): hw=idx>>6, t4=(idx>>4)&3, e=idx&15, nt=e>>1, j=e&1
//   p = nt>>1, gb = nt&1, gate = 2*gb + j, u = 16*hw + 4*t4 + p, g = gate*128+u
__global__ void ew_kernel(const float* __restrict__ emb,
                          const float* __restrict__ W_ih,
                          const float* __restrict__ b_ih,
                          const float* __restrict__ b_hh) {
    __shared__ float ev[Ec];
    int v = blockIdx.x;
    int idx = threadIdx.x;
    int hw = idx >> 6, t4p = (idx >> 4) & 3, e = idx & 15;
    int nt = e >> 1, j = e & 1;
    int p = nt >> 1, gb = nt & 1;
    int gate = 2 * gb + j;
    int u = 16 * hw + 4 * t4p + p;
    int g = gate * Hc + u;
    for (int ee = threadIdx.x; ee < Ec; ee += blockDim.x) ev[ee] = emb[v * Ec + ee];
    __syncthreads();
    float acc = b_ih[g] + b_hh[g];
    const float* w = W_ih + g * Ec;
#pragma unroll 8
    for (int ee = 0; ee < Ec; ee++) acc += w[ee] * ev[ee];
    d_EW2[v * EWST + idx] = __float2half(acc);
}

__global__ void mask_sum_kernel(const float* __restrict__ mask, int n) {
    double local = 0.0;
    for (int i = blockIdx.x * blockDim.x + threadIdx.x; i < n;
         i += gridDim.x * blockDim.x)
        local += (double)mask[i];
#pragma unroll
    for (int o = 16; o; o >>= 1) local += __shfl_down_sync(0xffffffffu, local, o);
    __shared__ double ws[32];
    int lane = threadIdx.x & 31, w = threadIdx.x >> 5;
    if (lane == 0) ws[w] = local;
    __syncthreads();
    if (w == 0) {
        local = (lane < (int)(blockDim.x >> 5)) ? ws[lane] : 0.0;
#pragma unroll
        for (int o = 16; o; o >>= 1) local += __shfl_down_sync(0xffffffffu, local, o);
        if (lane == 0) atomicAdd(&d_mask_sum, local);
    }
}

__device__ __forceinline__ uint32_t s2u(const void* p) {
    return (uint32_t)__cvta_generic_to_shared(p);
}
__device__ __forceinline__ __half2 tanh2(__half2 x) {
    uint32_t xi = *reinterpret_cast<uint32_t*>(&x), yi;
    asm("tanh.approx.f16x2 %0, %1;" : "=r"(yi) : "r"(xi));
    return *reinterpret_cast<__half2*>(&yi);
}
__device__ __forceinline__ __half2 sig2(__half2 x) {
    const __half2 hh = __float2half2_rn(0.5f);
    return __hfma2(tanh2(__hmul2(x, hh)), hh, hh);
}
__device__ __forceinline__ void barh(int id) {
    asm volatile("bar.sync %0, 256;" :: "r"(id) : "memory");
}

#define LDSM4(R, ADDR) \
    asm volatile("ldmatrix.sync.aligned.m8n8.x4.shared.b16 {%0,%1,%2,%3},[%4];" \
        : "=r"(R[0]),"=r"(R[1]),"=r"(R[2]),"=r"(R[3]) : "r"(ADDR))

// f16-accumulator MMA
#define MMAH16(D, A, b0, b1) \
    asm volatile("mma.sync.aligned.m16n8k16.row.col.f16.f16.f16.f16 " \
        "{%0,%1},{%2,%3,%4,%5},{%6,%7},{%0,%1};" \
        : "+r"(D[0]),"+r"(D[1]) \
        : "r"(A[0]),"r"(A[1]),"r"(A[2]),"r"(A[3]),"r"(b0),"r"(b1))

// SMEM layout (bytes)
#define SM_WHH   0                                   // f16 [512][PITCH]  139264
#define SM_H     (SM_WHH + Gc * PITCH * 2)           // f16 2x[32][PITCH]  17408
#define SM_WL    (SM_H + 2 * NBLK * PITCH * 2)       // f16 [32][PITCH]     8704
#define SM_EW    (SM_WL + 32 * PITCH * 2)            // f16 [30][544]      32640
#define SM_LOGH  (SM_EW + Vc * EWST * 2)             // f16 2x4x[32][36]   18432
#define SM_BL    (SM_LOGH + 2 * LOGH * 2)            // f32 [32]             128
#define SM_TOK   (SM_BL + 32 * 4)                    // u8  [32][128]       4096
#define SM_TOTAL (SM_TOK + NBLK * Tc)                //                   220672

__global__ void __launch_bounds__(NTHR, 1)
lstm_kernel(const int* __restrict__ inpt,
            const float* __restrict__ h0,
            const float* __restrict__ c0,
            const float* __restrict__ mask,
            const float* __restrict__ W_hh,
            const float* __restrict__ W_lin,
            const float* __restrict__ b_lin) {
    extern __shared__ char smem[];
    __half*        whh_s = (__half*)(smem + SM_WHH);
    __half*        h_s   = (__half*)(smem + SM_H);     // 2 buffers of [32][PITCH]
    __half*        wl_s  = (__half*)(smem + SM_WL);
    __half*        ew_s  = (__half*)(smem + SM_EW);
    __half*        log_h = (__half*)(smem + SM_LOGH);  // [par2][kq4][32][36]
    float*         bl_s  = (float*)(smem + SM_BL);
    unsigned char* tok_s = (unsigned char*)(smem + SM_TOK);

    const int tid  = threadIdx.x;
    const int lane = tid & 31;
    const int wid  = tid >> 5;       // 0..15
    const int half = wid >> 3;       // 0..1 : independent batch-half
    const int hw   = wid & 7;        // warp within half
    const int gid  = lane >> 2;      // 0..7
    const int t4   = lane & 3;       // 0..3
    const int b0   = blockIdx.x * NBLK;
    const int bid  = 1 + half;       // named barrier id

    // ---- stage W_hh -> f16, permuted [gp][k] ----
    for (int idx = tid; idx < Gc * Hc; idx += NTHR) {
        int g = idx >> 7, k = idx & 127;
        int u = g & 127, gate = g >> 7;
        int gp = 64 * (u >> 4) + 8 * (2 * (u & 3) + (gate >> 1))
               + 2 * ((u >> 2) & 3) + (gate & 1);
        whh_s[gp * PITCH + k] = __float2half(W_hh[idx]);
    }
    // ---- stage W_lin -> f16 [32 padded][k] ----
    for (int idx = tid; idx < 32 * Hc; idx += NTHR) {
        int v = idx >> 7, k = idx & 127;
        wl_s[v * PITCH + k] = (v < Vc) ? __float2half(W_lin[v * Hc + k])
                                       : __float2half(0.f);
    }
    // ---- stage h0 -> f16 buffer 0 ----
    for (int idx = tid; idx < NBLK * Hc; idx += NTHR) {
        int b = idx >> 7, u = idx & 127;
        h_s[b * PITCH + u] = __float2half(h0[(b0 + b) * Hc + u]);
    }
    // ---- EW packed table, biases, tokens ----
    {
        uint32_t* d32 = (uint32_t*)ew_s;
        const uint32_t* s32 = (const uint32_t*)d_EW2;
        for (int i = tid; i < Vc * EWST / 2; i += NTHR) d32[i] = s32[i];
    }
    if (tid < 32) bl_s[tid] = (tid < Vc) ? b_lin[tid] : 0.f;
    for (int idx = tid; idx < NBLK * Tc; idx += NTHR)
        tok_s[idx] = (unsigned char)inpt[b0 * Tc + idx];

    // ---- c state in half2: cr2[p] pairs rows (gid, gid+8), u = 16hw+4t4+p ----
    __half2 cr2[4];
#pragma unroll
    for (int p = 0; p < 4; p++) {
        float clo = c0[(b0 + 16 * half + gid) * Hc + 16 * hw + 4 * t4 + p];
        float chi = c0[(b0 + 16 * half + gid + 8) * Hc + 16 * hw + 4 * t4 + p];
        cr2[p] = __floats2half2_rn(clo, chi);
    }

    // ---- ldmatrix address patterns ----
    const int m = lane >> 3;   // 0..3
    const uint32_t hs_base = s2u(h_s);
    const uint32_t aA_pat =
        (((16 * half + (m & 1) * 8 + (lane & 7)) * PITCH + (m >> 1) * 8) << 1);
    const uint32_t aB_base = s2u(whh_s) +
        (((64 * hw + (m >> 1) * 8 + (lane & 7)) * PITCH + (m & 1) * 8) << 1);
#define ABQ(nq) (aB_base + (uint32_t)((nq) * (16 * PITCH * 2)))
    const int ew_off = hw * 64 + t4 * 16;
    const int l_nh = hw >> 2, l_kq = hw & 3;
    const uint32_t aBLm = s2u(wl_s) +
        (((16 * l_nh + (m >> 1) * 8 + (lane & 7)) * PITCH + (m & 1) * 8) << 1);
    const int hst_base = 16 * hw + 4 * t4;   // contiguous 4-u store base

    __syncthreads();   // staging visible to all

    // ---- cache B fragments for ks 0..3 : 64 regs ----
    uint32_t breg[4][16];
#pragma unroll
    for (int ks = 0; ks < 4; ks++)
#pragma unroll
        for (int nq = 0; nq < 4; nq++)
            LDSM4((&breg[ks][4 * nq]), ABQ(nq) + ks * 32);

    // ---- cache logits-B fragments (loop-invariant): this warp's 2 ks ----
    uint32_t lbr[8];
    LDSM4((&lbr[0]), aBLm + (2 * l_kq) * 32);
    LDSM4((&lbr[4]), aBLm + (2 * l_kq + 1) * 32);

    float my_loss = 0.f;

    // store this warp's f16 logits partials to parity buffer
    auto store_dlog = [&](uint32_t dl0[2], uint32_t dl1[2], int par) {
        __half* lout = log_h + par * LOGH + l_kq * KQH + (16 * half) * 36;
        int v0 = 16 * l_nh + 2 * t4;
        *(uint32_t*)&lout[gid * 36 + v0]           = dl0[0];
        *(uint32_t*)&lout[(gid + 8) * 36 + v0]     = dl0[1];
        *(uint32_t*)&lout[gid * 36 + v0 + 8]       = dl1[0];
        *(uint32_t*)&lout[(gid + 8) * 36 + v0 + 8] = dl1[1];
    };

    // CE over parity pb for this half's rows; y = tok[:,ty], m = mask[:,tm]
    auto ce_pass = [&](int pb, int ty, int tm) {
#pragma unroll
        for (int bi = 0; bi < 2; bi++) {
            int row = 16 * half + 2 * hw + bi;
            const __half* lb = log_h + pb * LOGH + row * 36;
            float lg;
            if (lane < Vc) {
                lg = bl_s[lane]
                   + __half2float(lb[lane])
                   + __half2float(lb[KQH + lane])
                   + __half2float(lb[2 * KQH + lane])
                   + __half2float(lb[3 * KQH + lane]);
            } else lg = -1e30f;
            float mx = lg;
#pragma unroll
            for (int o = 16; o; o >>= 1)
                mx = fmaxf(mx, __shfl_xor_sync(0xffffffffu, mx, o));
            float ex = (lane < Vc) ? __expf(lg - mx) : 0.f;
            float sm = ex;
#pragma unroll
            for (int o = 16; o; o >>= 1)
                sm += __shfl_xor_sync(0xffffffffu, sm, o);
            int y = (int)tok_s[row * Tc + ty];
            float ly = __shfl_sync(0xffffffffu, lg, y);
            if (lane == 0)
                my_loss += (mx + __logf(sm) - ly) * mask[(b0 + row) * Tc + tm];
        }
    };

#pragma unroll 1
    for (int t = 0; t < Tc - 1; t++) {
        const int cur = t & 1, nxt = cur ^ 1;

        // ---- prefetch EW + tokens (static tables; hides under barrier) ----
        int tok_lo = tok_s[(16 * half + gid) * Tc + t];
        int tok_hi = tok_s[(16 * half + gid + 8) * Tc + t];
        uint4 qa  = *(const uint4*)&ew_s[tok_lo * EWST + ew_off];
        uint4 qa2 = *(const uint4*)&ew_s[tok_lo * EWST + ew_off + 8];
        uint4 qb  = *(const uint4*)&ew_s[tok_hi * EWST + ew_off];
        uint4 qb2 = *(const uint4*)&ew_s[tok_hi * EWST + ew_off + 8];

        barh(bid);   // this half's h / logits writes visible

        // ---- PHASE STAGGER: half 1 consumes CE before its MMA stream ----
        if (half == 1 && t > 1) ce_pass(nxt, t - 1, t - 2);

        // ---- accumulator init: packed EW words ARE f16-D fragments ----
        uint32_t d[8][2];
        {
            const uint32_t* pa  = &qa.x;
            const uint32_t* pa2 = &qa2.x;
            const uint32_t* pb  = &qb.x;
            const uint32_t* pb2 = &qb2.x;
#pragma unroll
            for (int nt = 0; nt < 4; nt++) {
                d[nt][0]     = pa[nt];  d[nt][1]     = pb[nt];
                d[nt + 4][0] = pa2[nt]; d[nt + 4][1] = pb2[nt];
            }
        }
        uint32_t dl0[2] = {0u, 0u}, dl1[2] = {0u, 0u};

        // ---- gates MMA + merged logits: A LDSM per ks ----
        const uint32_t aAc = hs_base + cur * (HBE * 2) + aA_pat;
#pragma unroll
        for (int ks = 0; ks < 8; ks++) {
            uint32_t A[4];
            LDSM4(A, aAc + ks * 32);
            if (ks < 4) {
#pragma unroll
                for (int nq = 0; nq < 4; nq++) {
                    MMAH16(d[2 * nq],     A, breg[ks][4*nq],   breg[ks][4*nq+1]);
                    MMAH16(d[2 * nq + 1], A, breg[ks][4*nq+2], breg[ks][4*nq+3]);
                }
            } else {
#pragma unroll
                for (int nq = 0; nq < 4; nq++) {
                    uint32_t B[4];
                    LDSM4(B, ABQ(nq) + ks * 32);
                    MMAH16(d[2 * nq],     A, B[0], B[1]);
                    MMAH16(d[2 * nq + 1], A, B[2], B[3]);
                }
            }
            if ((ks >> 1) == l_kq) {   // this warp's logits k-slice (B cached)
                const uint32_t* L = (ks & 1) ? (lbr + 4) : lbr;
                MMAH16(dl0, A, L[0], L[1]);
                MMAH16(dl1, A, L[2], L[3]);
            }
        }

        // ---- CRITICAL PATH FIRST: LSTM cell (pure f16x2) + h writeback ----
        __half* hn = h_s + nxt * HBE;
        __half2 hhp[4];
#pragma unroll
        for (int p = 0; p < 4; p++) {
            __half2 rif_lo = *(__half2*)&d[2 * p][0];      // (i,f) row gid
            __half2 rif_hi = *(__half2*)&d[2 * p][1];      // (i,f) row gid+8
            __half2 rgo_lo = *(__half2*)&d[2 * p + 1][0];  // (g,o) row gid
            __half2 rgo_hi = *(__half2*)&d[2 * p + 1][1];  // (g,o) row gid+8
            __half2 i2 = __lows2half2(rif_lo, rif_hi);
            __half2 f2 = __highs2half2(rif_lo, rif_hi);
            __half2 g2 = __lows2half2(rgo_lo, rgo_hi);
            __half2 o2 = __highs2half2(rgo_lo, rgo_hi);
            __half2 c2 = __hfma2(sig2(f2), cr2[p], __hmul2(sig2(i2), tanh2(g2)));
            cr2[p] = c2;
            hhp[p] = __hmul2(sig2(o2), tanh2(c2));
        }
        {
            __half2 lo01 = __lows2half2(hhp[0], hhp[1]);
            __half2 lo23 = __lows2half2(hhp[2], hhp[3]);
            __half2 hi01 = __highs2half2(hhp[0], hhp[1]);
            __half2 hi23 = __highs2half2(hhp[2], hhp[3]);
            uint2 lo = make_uint2(*(uint32_t*)&lo01, *(uint32_t*)&lo23);
            uint2 hi = make_uint2(*(uint32_t*)&hi01, *(uint32_t*)&hi23);
            *(uint2*)&hn[(16 * half + gid) * PITCH + hst_base]     = lo;
            *(uint2*)&hn[(16 * half + gid + 8) * PITCH + hst_base] = hi;
        }

        // ---- off-critical-path: logits store; half 0 CE fills barrier slack ----
        store_dlog(dl0, dl1, cur);     // logits(h_t) partials -> parity cur
        if (half == 0 && t > 1) ce_pass(nxt, t - 1, t - 2);
    }

    // ---- tail: logits(h_127) (buffer 1 -> parity 1); consume s=126,127 ----
    barh(bid);
    {
        uint32_t dl0[2] = {0u, 0u}, dl1[2] = {0u, 0u};
        uint32_t aA = hs_base + 1 * (HBE * 2) + aA_pat;
#pragma unroll
        for (int kk = 0; kk < 2; kk++) {
            int ksl = 2 * l_kq + kk;
            uint32_t A[4];
            LDSM4(A, aA + ksl * 32);
            const uint32_t* L = kk ? (lbr + 4) : lbr;
            MMAH16(dl0, A, L[0], L[1]);
            MMAH16(dl1, A, L[2], L[3]);
        }
        store_dlog(dl0, dl1, 1);
    }
    ce_pass(0, Tc - 2, Tc - 3);   // logits(h_126) in parity 0
    barh(bid);
    ce_pass(1, Tc - 1, Tc - 2);

    // ---- block loss reduction ----
#pragma unroll
    for (int o = 16; o; o >>= 1)
        my_loss += __shfl_xor_sync(0xffffffffu, my_loss, o);
    __shared__ float wsum[16];
    if (lane == 0) wsum[wid] = my_loss;
    __syncthreads();
    if (wid == 0) {
        float v = (lane < 16) ? wsum[lane] : 0.f;
#pragma unroll
        for (int o = 8; o; o >>= 1)
            v += __shfl_xor_sync(0xffffffffu, v, o);
        if (lane == 0) atomicAdd(&d_loss_sum, (double)v);
    }
}

__global__ void finalize_kernel(float* out) {
    out[0] = (float)(d_loss_sum / d_mask_sum);
}

extern "C" void kernel_launch(void* const* d_in, const int* in_sizes, int n_in,
                              void* d_out, int out_size) {
    const int*   inpt  = (const int*)d_in[0];
    const float* h0    = (const float*)d_in[1];
    const float* c0    = (const float*)d_in[2];
    const float* mask  = (const float*)d_in[3];
    // d_in[4] = beta (unused)
    const float* emb   = (const float*)d_in[5];
    const float* W_ih  = (const float*)d_in[6];
    const float* b_ih  = (const float*)d_in[7];
    const float* W_hh  = (const float*)d_in[8];
    const float* b_hh  = (const float*)d_in[9];
    const float* W_lin = (const float*)d_in[10];
    const float* b_lin = (const float*)d_in[11];
    float* out = (float*)d_out;

    cudaFuncSetAttribute(lstm_kernel,
                         cudaFuncAttributeMaxDynamicSharedMemorySize, SM_TOTAL);

    zero_kernel<<<1, 1>>>();
    mask_sum_kernel<<<256, 256>>>(mask, Bc * Tc);
    ew_kernel<<<Vc, NTHR>>>(emb, W_ih, b_ih, b_hh);
    lstm_kernel<<<Bc / NBLK, NTHR, SM_TOTAL>>>(inpt, h0, c0, mask,
                                               W_hh, W_lin, b_lin);
    finalize_kernel<<<1, 1>>>(out);
}